// round 8
// baseline (speedup 1.0000x reference)
#include <cuda_runtime.h>
#include <stdint.h>

// Instant-NGP hash grid encode — dense pair-duplicated table, fused pair loads.
// B=524288 points, D=3, L=16 levels, C=2, H=16, hashed table size 2^19.
//
// Evidence trail: L1tex wavefronts bind (~92% SOL). Best measured load
// structure (R6): divergent pair_load = fused LDG.128 when i0^i1==1, else
// 2x LDG.64. R7's always-wide scheme regressed. R8: repack dense levels as
// overlapping chunks chunk[s]=(e[s],e[s+1]) -> dense pairs ALWAYS fuse
// (indices 2s,2s+1); hashed levels even-base aligned (fuse prob 1/2).
// Expected scattered accesses/thread: 6.0 -> 5.625. launch_bounds caps regs
// for ~87% occupancy (was 64.7% at regs=40).

#define NPOINTS  524288
#define NLEVELS  16
#define NPAIRS   (NPOINTS * NLEVELS)

// src level offsets: 0, 4913, 40850, 315475, then +524288 per hashed level.
// dst layout (float2 units):
//   dense level l: base = 2*src_off[l], size = 2*entries (chunk per entry)
//   hashed level:  base = 2*315475 + h*524288 (even), straight copy
#define N_DENSE_CHUNKS 315475          // == src dense entry total
#define TOTAL_DST      7446694         // 2*315475 + 13*524288

__device__ __align__(16) float2 g_emb[TOTAL_DST];

__constant__ int c_dst_off[16] = {
    0, 9826, 81700, 630950,
    1155238, 1679526, 2203814, 2728102,
    3252390, 3776678, 4300966, 4825254,
    5349542, 5873830, 6398118, 6922406
};

__global__ __launch_bounds__(256)
void repack_kernel(const float2* __restrict__ src)
{
    int t2 = blockIdx.x * blockDim.x + threadIdx.x;   // dst chunk (float4) idx
    if (t2 >= TOTAL_DST / 2) return;
    int a, bidx;
    if (t2 < N_DENSE_CHUNKS) {
        // dense: chunk[t2] = (src[t2], src[t2+1]) within the level;
        // clamp at level end (hi half of last chunk is never read)
        int end = (t2 < 4913) ? 4913 : (t2 < 40850) ? 40850 : 315475;
        a = t2;
        bidx = (t2 + 1 < end) ? (t2 + 1) : (end - 1);
    } else {
        // hashed: straight copy, dst float2 2*t2 <- src (2*t2 - 315475)
        a = 2 * t2 - N_DENSE_CHUNKS;
        bidx = a + 1;
    }
    float2 A = __ldg(&src[a]);
    float2 B = __ldg(&src[bidx]);
    reinterpret_cast<float4*>(g_emb)[t2] = make_float4(A.x, A.y, B.x, B.y);
}

// Load corners (i0, i1). If they share an aligned 16B chunk, one LDG.128;
// else two LDG.64. (Measured best structure — do not widen unfused loads.)
__device__ __forceinline__ void pair_load(const float2* __restrict__ tab,
                                          uint32_t i0, uint32_t i1,
                                          float2& v0, float2& v1)
{
    if ((i0 ^ i1) == 1u) {
        const float4 q = __ldg(reinterpret_cast<const float4*>(tab + (i0 & ~1u)));
        const float2 lo = make_float2(q.x, q.y);
        const float2 hi = make_float2(q.z, q.w);
        bool odd = (i0 & 1u) != 0u;
        v0 = odd ? hi : lo;
        v1 = odd ? lo : hi;
    } else {
        v0 = __ldg(tab + i0);
        v1 = __ldg(tab + i1);
    }
}

__global__ __launch_bounds__(256, 7)
void hash_encode_kernel(const float* __restrict__ in,
                        float2* __restrict__ out)
{
    int tid = blockIdx.x * blockDim.x + threadIdx.x;
    if (tid >= NPAIRS) return;

    int b = tid >> 4;
    int l = tid & 15;

    // map [-1,1) -> [0,1)
    float x = (__ldg(&in[b * 3 + 0]) + 1.0f) * 0.5f;
    float y = (__ldg(&in[b * 3 + 1]) + 1.0f) * 0.5f;
    float z = (__ldg(&in[b * 3 + 2]) + 1.0f) * 0.5f;

    uint32_t res = 16u << l;
    float fres = (float)res;

    float px = x * fres, py = y * fres, pz = z * fres;
    float gx = floorf(px), gy = floorf(py), gz = floorf(pz);
    float fx = px - gx,   fy = py - gy,   fz = pz - gz;
    uint32_t ux = (uint32_t)gx, uy = (uint32_t)gy, uz = (uint32_t)gz;

    // hashed-form partials: idx = (ux*1 ^ uy*P1 ^ uz*P2) & (2^19 - 1)
    const uint32_t P1 = 2654435761u;
    const uint32_t P2 = 805459861u;
    uint32_t hx0 = ux;        uint32_t hx1 = ux + 1u;
    uint32_t hy0 = uy * P1;   uint32_t hy1 = hy0 + P1;
    uint32_t hz0 = uz * P2;   uint32_t hz1 = hz0 + P2;

    // dense-form partials (duplicated layout): pair = (2s, 2s+1),
    // s = ux + uy*(res+1) + uz*(res+1)^2, provably in range (x < 1 strictly)
    uint32_t r1 = res + 1u;
    uint32_t r2 = r1 * r1;
    uint32_t sy0 = uy * r1;  uint32_t sy1 = sy0 + r1;
    uint32_t sz0 = uz * r2;  uint32_t sz1 = sz0 + r2;

    bool hashed = (l >= 3);
    const float2* __restrict__ tab = g_emb + c_dst_off[l];

    // corner c = xbit | (ybit<<1) | (zbit<<2); pair p = ybit | (zbit<<1)
    float2 v[8];
#pragma unroll
    for (int p = 0; p < 4; p++) {
        uint32_t hyz = ((p & 1) ? hy1 : hy0) ^ ((p & 2) ? hz1 : hz0);
        uint32_t ih0 = (hx0 ^ hyz) & 0x7FFFFu;
        uint32_t ih1 = (hx1 ^ hyz) & 0x7FFFFu;
        uint32_t s2  = (((p & 1) ? sy1 : sy0) + ((p & 2) ? sz1 : sz0) + ux) << 1;
        uint32_t i0 = hashed ? ih0 : s2;
        uint32_t i1 = hashed ? ih1 : (s2 + 1u);
        pair_load(tab, i0, i1, v[2 * p], v[2 * p + 1]);
    }

    // trilinear weights
    float wx[2] = {1.0f - fx, fx};
    float wy[2] = {1.0f - fy, fy};
    float wz[2] = {1.0f - fz, fz};

    float ax = 0.0f, ay = 0.0f;
#pragma unroll
    for (int c = 0; c < 8; c++) {
        float w = wx[c & 1] * wy[(c >> 1) & 1] * wz[c >> 2];
        ax = fmaf(w, v[c].x, ax);
        ay = fmaf(w, v[c].y, ay);
    }

    out[tid] = make_float2(ax, ay);
}

extern "C" void kernel_launch(void* const* d_in, const int* in_sizes, int n_in,
                              void* d_out, int out_size)
{
    const float*  inputs = (const float*)d_in[0];
    const float2* emb    = (const float2*)d_in[1];
    float2*       out    = (float2*)d_out;

    // 1) repack: dense levels pair-duplicated, hashed levels even-base copy.
    //    Idempotent, deterministic, graph-capturable.
    {
        int nthreads = TOTAL_DST / 2;
        repack_kernel<<<(nthreads + 255) / 256, 256>>>(emb);
    }

    // 2) gather/interpolate
    hash_encode_kernel<<<(NPAIRS + 255) / 256, 256>>>(inputs, out);
}

// round 9
// speedup vs baseline: 1.0988x; 1.0988x over previous
#include <cuda_runtime.h>
#include <stdint.h>

// Instant-NGP hash grid encode — R6 structure (best measured gather) + occupancy cap.
// B=524288 points, D=3, L=16 levels, C=2, H=16, hashed table size 2^19.
//
// Evidence trail:
//  - L1tex wavefronts bind (~92% SOL); gather sits on the 50.3M-wavefront model.
//  - Best load structure (R6): fused LDG.128 when i0^i1==1 (prob 1/2, needs
//    even-base repack), else 2x LDG.64. Always-wide (R7) and dense-duplicated
//    (R8, cache-density loss -> DRAM up 50%) both regressed.
//  - R6's regs=40 cost occupancy (64.7%); same structure fits 32 regs under
//    __launch_bounds__(256,7) (proven in R8). This round = R6 + the cap.

#define NPOINTS  524288
#define NLEVELS  16
#define NPAIRS   (NPOINTS * NLEVELS)

// src level offsets: 0,4913,40850,315475, then +524288 each
// dst (aligned) offsets: pad levels 0..2 by one entry so every base is even
#define TOTAL_DST 7131222

__device__ __align__(16) float2 g_emb[TOTAL_DST];

__constant__ int c_dst_off[16] = {
    0, 4914, 40852, 315478,
    839766, 1364054, 1888342, 2412630,
    2936918, 3461206, 3985494, 4509782,
    5034070, 5558358, 6082646, 6606934
};

__device__ __forceinline__ int repack_shift(int t) {
    return (t >= 315478) ? 3 : (t >= 40852) ? 2 : (t >= 4914) ? 1 : 0;
}

__global__ __launch_bounds__(256)
void repack_kernel(const float2* __restrict__ src)
{
    int t = (blockIdx.x * blockDim.x + threadIdx.x) * 2;  // TOTAL_DST is even
    if (t >= TOTAL_DST) return;
    float2 a = __ldg(&src[t     - repack_shift(t)]);
    float2 b = __ldg(&src[t + 1 - repack_shift(t + 1)]);
    *reinterpret_cast<float4*>(&g_emb[t]) = make_float4(a.x, a.y, b.x, b.y);
}

// Load corners (i0, i1). If they share an aligned 16B chunk, one LDG.128;
// else two LDG.64. (Measured best structure — do not widen unfused loads.)
__device__ __forceinline__ void pair_load(const float2* __restrict__ tab,
                                          uint32_t i0, uint32_t i1,
                                          float2& v0, float2& v1)
{
    if ((i0 ^ i1) == 1u) {
        const float4 q = __ldg(reinterpret_cast<const float4*>(tab + (i0 & ~1u)));
        const float2 lo = make_float2(q.x, q.y);
        const float2 hi = make_float2(q.z, q.w);
        bool odd = (i0 & 1u) != 0u;
        v0 = odd ? hi : lo;
        v1 = odd ? lo : hi;
    } else {
        v0 = __ldg(tab + i0);
        v1 = __ldg(tab + i1);
    }
}

__global__ __launch_bounds__(256, 7)
void hash_encode_kernel(const float* __restrict__ in,
                        float2* __restrict__ out)
{
    int tid = blockIdx.x * blockDim.x + threadIdx.x;
    if (tid >= NPAIRS) return;

    int b = tid >> 4;
    int l = tid & 15;

    // map [-1,1) -> [0,1)
    float x = (__ldg(&in[b * 3 + 0]) + 1.0f) * 0.5f;
    float y = (__ldg(&in[b * 3 + 1]) + 1.0f) * 0.5f;
    float z = (__ldg(&in[b * 3 + 2]) + 1.0f) * 0.5f;

    uint32_t res = 16u << l;
    float fres = (float)res;

    float px = x * fres, py = y * fres, pz = z * fres;
    float gx = floorf(px), gy = floorf(py), gz = floorf(pz);
    float fx = px - gx,   fy = py - gy,   fz = pz - gz;
    uint32_t ux = (uint32_t)gx, uy = (uint32_t)gy, uz = (uint32_t)gz;

    // hashed-form partials: idx = (ux*1 ^ uy*P1 ^ uz*P2) & (2^19 - 1)
    const uint32_t P1 = 2654435761u;
    const uint32_t P2 = 805459861u;
    uint32_t hx0 = ux;        uint32_t hx1 = ux + 1u;
    uint32_t hy0 = uy * P1;   uint32_t hy1 = hy0 + P1;
    uint32_t hz0 = uz * P2;   uint32_t hz1 = hz0 + P2;

    // dense-form partials: idx = ux + uy*(res+1) + uz*(res+1)^2 (in range,
    // x < 1 strictly). Garbage for hashed lanes; selected away below.
    uint32_t r1 = res + 1u;
    uint32_t r2 = r1 * r1;
    uint32_t sy0 = uy * r1;  uint32_t sy1 = sy0 + r1;
    uint32_t sz0 = uz * r2;  uint32_t sz1 = sz0 + r2;

    bool hashed = (l >= 3);
    const float2* __restrict__ tab = g_emb + c_dst_off[l];

    // corner c = xbit | (ybit<<1) | (zbit<<2); pair p = ybit | (zbit<<1)
    float2 v[8];
#pragma unroll
    for (int p = 0; p < 4; p++) {
        uint32_t hyz = ((p & 1) ? hy1 : hy0) ^ ((p & 2) ? hz1 : hz0);
        uint32_t ih0 = (hx0 ^ hyz) & 0x7FFFFu;
        uint32_t ih1 = (hx1 ^ hyz) & 0x7FFFFu;
        uint32_t s   = ((p & 1) ? sy1 : sy0) + ((p & 2) ? sz1 : sz0) + ux;
        uint32_t i0 = hashed ? ih0 : s;
        uint32_t i1 = hashed ? ih1 : (s + 1u);
        pair_load(tab, i0, i1, v[2 * p], v[2 * p + 1]);
    }

    // trilinear weights
    float wx[2] = {1.0f - fx, fx};
    float wy[2] = {1.0f - fy, fy};
    float wz[2] = {1.0f - fz, fz};

    float ax = 0.0f, ay = 0.0f;
#pragma unroll
    for (int c = 0; c < 8; c++) {
        float w = wx[c & 1] * wy[(c >> 1) & 1] * wz[c >> 2];
        ax = fmaf(w, v[c].x, ax);
        ay = fmaf(w, v[c].y, ay);
    }

    out[tid] = make_float2(ax, ay);
}

extern "C" void kernel_launch(void* const* d_in, const int* in_sizes, int n_in,
                              void* d_out, int out_size)
{
    const float*  inputs = (const float*)d_in[0];
    const float2* emb    = (const float2*)d_in[1];
    float2*       out    = (float2*)d_out;

    // 1) repack table into even-base (16B-aligned) layout. Idempotent,
    //    deterministic, graph-capturable.
    {
        int nthreads = TOTAL_DST / 2;
        repack_kernel<<<(nthreads + 255) / 256, 256>>>(emb);
    }

    // 2) gather/interpolate
    hash_encode_kernel<<<(NPAIRS + 255) / 256, 256>>>(inputs, out);
}

// round 10
// speedup vs baseline: 1.1115x; 1.0116x over previous
#include <cuda_runtime.h>
#include <stdint.h>

// Instant-NGP hash grid encode — R9 structure + cache-policy hygiene.
// B=524288 points, D=3, L=16 levels, C=2, H=16, hashed table size 2^19.
//
// Evidence trail:
//  - Gather is saturated at ~0.98 of the 1 wf/cyc/SM L1tex wavefront ceiling
//    (52.4M scattered accesses). Fused pair loads (LDG.128 when i0^i1==1,
//    prob 1/2 after even-base repack) are the measured-best structure; R7
//    (always-wide) and R8 (dense duplication -> L2 capacity blowout) regressed.
//  - Repack (~10.5us) buys ~21us of fusion; near its own bandwidth floor.
//  - R10: __stcs output stores (evict-first: keep 57MB table L2-resident),
//    __ldcs repack source reads, occ 86% -> 100% (regs naturally 32).

#define NPOINTS  524288
#define NLEVELS  16
#define NPAIRS   (NPOINTS * NLEVELS)

// src level offsets: 0,4913,40850,315475, then +524288 each
// dst (aligned) offsets: pad levels 0..2 by one entry so every base is even
#define TOTAL_DST 7131222

__device__ __align__(16) float2 g_emb[TOTAL_DST];

__constant__ int c_dst_off[16] = {
    0, 4914, 40852, 315478,
    839766, 1364054, 1888342, 2412630,
    2936918, 3461206, 3985494, 4509782,
    5034070, 5558358, 6082646, 6606934
};

__device__ __forceinline__ int repack_shift(int t) {
    return (t >= 315478) ? 3 : (t >= 40852) ? 2 : (t >= 4914) ? 1 : 0;
}

__global__ __launch_bounds__(256)
void repack_kernel(const float2* __restrict__ src)
{
    int t = (blockIdx.x * blockDim.x + threadIdx.x) * 2;  // TOTAL_DST is even
    if (t >= TOTAL_DST) return;
    // streaming reads: src is read-once, don't evict the dst table from L2
    float2 a = __ldcs(&src[t     - repack_shift(t)]);
    float2 b = __ldcs(&src[t + 1 - repack_shift(t + 1)]);
    *reinterpret_cast<float4*>(&g_emb[t]) = make_float4(a.x, a.y, b.x, b.y);
}

// Load corners (i0, i1). If they share an aligned 16B chunk, one LDG.128;
// else two LDG.64. (Measured best structure — do not widen unfused loads.)
__device__ __forceinline__ void pair_load(const float2* __restrict__ tab,
                                          uint32_t i0, uint32_t i1,
                                          float2& v0, float2& v1)
{
    if ((i0 ^ i1) == 1u) {
        const float4 q = __ldg(reinterpret_cast<const float4*>(tab + (i0 & ~1u)));
        const float2 lo = make_float2(q.x, q.y);
        const float2 hi = make_float2(q.z, q.w);
        bool odd = (i0 & 1u) != 0u;
        v0 = odd ? hi : lo;
        v1 = odd ? lo : hi;
    } else {
        v0 = __ldg(tab + i0);
        v1 = __ldg(tab + i1);
    }
}

__global__ __launch_bounds__(256, 8)
void hash_encode_kernel(const float* __restrict__ in,
                        float2* __restrict__ out)
{
    int tid = blockIdx.x * blockDim.x + threadIdx.x;
    if (tid >= NPAIRS) return;

    int b = tid >> 4;
    int l = tid & 15;

    // map [-1,1) -> [0,1)
    float x = (__ldg(&in[b * 3 + 0]) + 1.0f) * 0.5f;
    float y = (__ldg(&in[b * 3 + 1]) + 1.0f) * 0.5f;
    float z = (__ldg(&in[b * 3 + 2]) + 1.0f) * 0.5f;

    uint32_t res = 16u << l;
    float fres = (float)res;

    float px = x * fres, py = y * fres, pz = z * fres;
    float gx = floorf(px), gy = floorf(py), gz = floorf(pz);
    float fx = px - gx,   fy = py - gy,   fz = pz - gz;
    uint32_t ux = (uint32_t)gx, uy = (uint32_t)gy, uz = (uint32_t)gz;

    // hashed-form partials: idx = (ux*1 ^ uy*P1 ^ uz*P2) & (2^19 - 1)
    const uint32_t P1 = 2654435761u;
    const uint32_t P2 = 805459861u;
    uint32_t hx0 = ux;        uint32_t hx1 = ux + 1u;
    uint32_t hy0 = uy * P1;   uint32_t hy1 = hy0 + P1;
    uint32_t hz0 = uz * P2;   uint32_t hz1 = hz0 + P2;

    // dense-form partials: idx = ux + uy*(res+1) + uz*(res+1)^2 (in range,
    // x < 1 strictly). Garbage for hashed lanes; selected away below.
    uint32_t r1 = res + 1u;
    uint32_t r2 = r1 * r1;
    uint32_t sy0 = uy * r1;  uint32_t sy1 = sy0 + r1;
    uint32_t sz0 = uz * r2;  uint32_t sz1 = sz0 + r2;

    bool hashed = (l >= 3);
    const float2* __restrict__ tab = g_emb + c_dst_off[l];

    // corner c = xbit | (ybit<<1) | (zbit<<2); pair p = ybit | (zbit<<1)
    float2 v[8];
#pragma unroll
    for (int p = 0; p < 4; p++) {
        uint32_t hyz = ((p & 1) ? hy1 : hy0) ^ ((p & 2) ? hz1 : hz0);
        uint32_t ih0 = (hx0 ^ hyz) & 0x7FFFFu;
        uint32_t ih1 = (hx1 ^ hyz) & 0x7FFFFu;
        uint32_t s   = ((p & 1) ? sy1 : sy0) + ((p & 2) ? sz1 : sz0) + ux;
        uint32_t i0 = hashed ? ih0 : s;
        uint32_t i1 = hashed ? ih1 : (s + 1u);
        pair_load(tab, i0, i1, v[2 * p], v[2 * p + 1]);
    }

    // trilinear weights
    float wx[2] = {1.0f - fx, fx};
    float wy[2] = {1.0f - fy, fy};
    float wz[2] = {1.0f - fz, fz};

    float ax = 0.0f, ay = 0.0f;
#pragma unroll
    for (int c = 0; c < 8; c++) {
        float w = wx[c & 1] * wy[(c >> 1) & 1] * wz[c >> 2];
        ax = fmaf(w, v[c].x, ax);
        ay = fmaf(w, v[c].y, ay);
    }

    // streaming store: output is write-once; evict-first keeps the 57MB
    // table resident in L2 instead of churning it with output lines.
    __stcs(&out[tid], make_float2(ax, ay));
}

extern "C" void kernel_launch(void* const* d_in, const int* in_sizes, int n_in,
                              void* d_out, int out_size)
{
    const float*  inputs = (const float*)d_in[0];
    const float2* emb    = (const float2*)d_in[1];
    float2*       out    = (float2*)d_out;

    // 1) repack table into even-base (16B-aligned) layout. Idempotent,
    //    deterministic, graph-capturable.
    {
        int nthreads = TOTAL_DST / 2;
        repack_kernel<<<(nthreads + 255) / 256, 256>>>(emb);
    }

    // 2) gather/interpolate
    hash_encode_kernel<<<(NPAIRS + 255) / 256, 256>>>(inputs, out);
}

// round 12
// speedup vs baseline: 1.1125x; 1.0008x over previous
#include <cuda_runtime.h>
#include <stdint.h>

// Instant-NGP hash grid encode — fused pair loads + cache hygiene, natural regs.
// B=524288 points, D=3, L=16 levels, C=2, H=16, hashed table size 2^19.
//
// Evidence trail:
//  - Gather binds on L1tex scattered-access wavefronts (~52M total).
//  - Best load structure: fused LDG.128 when i0^i1==1 (prob 1/2, even-base
//    repack required), else 2x LDG.64. Always-wide (R7) and dense-duplication
//    (R8, L2 capacity blowout) both regressed.
//  - regs=40/occ=65% (R6) measured faster than regs=32/occ=86% (R9/R10):
//    the 32-reg cap serializes load batching (MLP down); per-warp MLP is the
//    binding concurrency term, not warp count. R11 = R10 without the cap.
//  - __stcs output (evict-first; keep 57MB table L2-resident), __ldcs repack.

#define NPOINTS  524288
#define NLEVELS  16
#define NPAIRS   (NPOINTS * NLEVELS)

// src level offsets: 0,4913,40850,315475, then +524288 each
// dst (aligned) offsets: pad levels 0..2 by one entry so every base is even
#define TOTAL_DST 7131222

__device__ __align__(16) float2 g_emb[TOTAL_DST];

__constant__ int c_dst_off[16] = {
    0, 4914, 40852, 315478,
    839766, 1364054, 1888342, 2412630,
    2936918, 3461206, 3985494, 4509782,
    5034070, 5558358, 6082646, 6606934
};

__device__ __forceinline__ int repack_shift(int t) {
    return (t >= 315478) ? 3 : (t >= 40852) ? 2 : (t >= 4914) ? 1 : 0;
}

__global__ __launch_bounds__(256)
void repack_kernel(const float2* __restrict__ src)
{
    int t = (blockIdx.x * blockDim.x + threadIdx.x) * 2;  // TOTAL_DST is even
    if (t >= TOTAL_DST) return;
    // streaming reads: src is read-once, don't evict the dst table from L2
    float2 a = __ldcs(&src[t     - repack_shift(t)]);
    float2 b = __ldcs(&src[t + 1 - repack_shift(t + 1)]);
    *reinterpret_cast<float4*>(&g_emb[t]) = make_float4(a.x, a.y, b.x, b.y);
}

// Load corners (i0, i1). If they share an aligned 16B chunk, one LDG.128;
// else two LDG.64. (Measured best structure — do not widen unfused loads.)
__device__ __forceinline__ void pair_load(const float2* __restrict__ tab,
                                          uint32_t i0, uint32_t i1,
                                          float2& v0, float2& v1)
{
    if ((i0 ^ i1) == 1u) {
        const float4 q = __ldg(reinterpret_cast<const float4*>(tab + (i0 & ~1u)));
        const float2 lo = make_float2(q.x, q.y);
        const float2 hi = make_float2(q.z, q.w);
        bool odd = (i0 & 1u) != 0u;
        v0 = odd ? hi : lo;
        v1 = odd ? lo : hi;
    } else {
        v0 = __ldg(tab + i0);
        v1 = __ldg(tab + i1);
    }
}

__global__ __launch_bounds__(256)
void hash_encode_kernel(const float* __restrict__ in,
                        float2* __restrict__ out)
{
    int tid = blockIdx.x * blockDim.x + threadIdx.x;
    if (tid >= NPAIRS) return;

    int b = tid >> 4;
    int l = tid & 15;

    // map [-1,1) -> [0,1)
    float x = (__ldg(&in[b * 3 + 0]) + 1.0f) * 0.5f;
    float y = (__ldg(&in[b * 3 + 1]) + 1.0f) * 0.5f;
    float z = (__ldg(&in[b * 3 + 2]) + 1.0f) * 0.5f;

    uint32_t res = 16u << l;
    float fres = (float)res;

    float px = x * fres, py = y * fres, pz = z * fres;
    float gx = floorf(px), gy = floorf(py), gz = floorf(pz);
    float fx = px - gx,   fy = py - gy,   fz = pz - gz;
    uint32_t ux = (uint32_t)gx, uy = (uint32_t)gy, uz = (uint32_t)gz;

    // hashed-form partials: idx = (ux*1 ^ uy*P1 ^ uz*P2) & (2^19 - 1)
    const uint32_t P1 = 2654435761u;
    const uint32_t P2 = 805459861u;
    uint32_t hx0 = ux;        uint32_t hx1 = ux + 1u;
    uint32_t hy0 = uy * P1;   uint32_t hy1 = hy0 + P1;
    uint32_t hz0 = uz * P2;   uint32_t hz1 = hz0 + P2;

    // dense-form partials: idx = ux + uy*(res+1) + uz*(res+1)^2 (in range,
    // x < 1 strictly). Garbage for hashed lanes; selected away below.
    uint32_t r1 = res + 1u;
    uint32_t r2 = r1 * r1;
    uint32_t sy0 = uy * r1;  uint32_t sy1 = sy0 + r1;
    uint32_t sz0 = uz * r2;  uint32_t sz1 = sz0 + r2;

    bool hashed = (l >= 3);
    const float2* __restrict__ tab = g_emb + c_dst_off[l];

    // corner c = xbit | (ybit<<1) | (zbit<<2); pair p = ybit | (zbit<<1)
    float2 v[8];
#pragma unroll
    for (int p = 0; p < 4; p++) {
        uint32_t hyz = ((p & 1) ? hy1 : hy0) ^ ((p & 2) ? hz1 : hz0);
        uint32_t ih0 = (hx0 ^ hyz) & 0x7FFFFu;
        uint32_t ih1 = (hx1 ^ hyz) & 0x7FFFFu;
        uint32_t s   = ((p & 1) ? sy1 : sy0) + ((p & 2) ? sz1 : sz0) + ux;
        uint32_t i0 = hashed ? ih0 : s;
        uint32_t i1 = hashed ? ih1 : (s + 1u);
        pair_load(tab, i0, i1, v[2 * p], v[2 * p + 1]);
    }

    // trilinear weights
    float wx[2] = {1.0f - fx, fx};
    float wy[2] = {1.0f - fy, fy};
    float wz[2] = {1.0f - fz, fz};

    float ax = 0.0f, ay = 0.0f;
#pragma unroll
    for (int c = 0; c < 8; c++) {
        float w = wx[c & 1] * wy[(c >> 1) & 1] * wz[c >> 2];
        ax = fmaf(w, v[c].x, ax);
        ay = fmaf(w, v[c].y, ay);
    }

    // streaming store: output is write-once; evict-first keeps the 57MB
    // table resident in L2 instead of churning it with output lines.
    __stcs(&out[tid], make_float2(ax, ay));
}

extern "C" void kernel_launch(void* const* d_in, const int* in_sizes, int n_in,
                              void* d_out, int out_size)
{
    const float*  inputs = (const float*)d_in[0];
    const float2* emb    = (const float2*)d_in[1];
    float2*       out    = (float2*)d_out;

    // 1) repack table into even-base (16B-aligned) layout. Idempotent,
    //    deterministic, graph-capturable.
    {
        int nthreads = TOTAL_DST / 2;
        repack_kernel<<<(nthreads + 255) / 256, 256>>>(emb);
    }

    // 2) gather/interpolate
    hash_encode_kernel<<<(NPAIRS + 255) / 256, 256>>>(inputs, out);
}

// round 14
// speedup vs baseline: 1.1284x; 1.0143x over previous
#include <cuda_runtime.h>
#include <cuda_fp16.h>
#include <stdint.h>

// Instant-NGP hash grid encode — fp16 pair-duplicated table.
// B=524288 points, D=3, L=16 levels, C=2, H=16, hashed table size 2^19.
//
// Evidence trail:
//  - Gather pinned at ~98% of L1tex scattered-wavefront ceiling across
//    regs/occupancy variants; only wavefront COUNT can reduce time.
//  - R13: table entry D[g] = (fp16x2(e[g]), fp16x2(e[g+1])) — 8B/entry, so
//    the duplicated table keeps the ORIGINAL 57MB footprint (R8's fp32
//    duplication blew L2; fp16 makes duplication footprint-neutral).
//    Dense pairs (s,s+1): ALWAYS one 8B load. Hashed pairs {2m,2m+1}
//    (prob 1/2): one 8B load; else two 4B lo-half loads.
//    Expected scattered accesses/thread: 6.0 -> 5.625; sectors halved.
//  - Accuracy: values +-1e-4; per-corner rounding rms ~1.7e-8 abs, output
//    norm rel_err ~3e-4 < 1e-3 gate (~3x margin).

#define NPOINTS  524288
#define NLEVELS  16
#define NPAIRS   (NPOINTS * NLEVELS)
#define TOTAL_SRC 7131219

// D[g] = (h2(e[g]), h2(e[g+1])), 8B each, original (unpadded) level offsets.
__device__ __align__(16) uint2 g_emb[TOTAL_SRC];

__constant__ int c_off[16] = {
    0, 4913, 40850, 315475,
    839763, 1364051, 1888339, 2412627,
    2936915, 3461203, 3985491, 4509779,
    5034067, 5558355, 6082643, 6606931
};

__device__ __forceinline__ uint32_t f22h2(float2 v) {
    __half2 h = __floats2half2_rn(v.x, v.y);
    return *reinterpret_cast<uint32_t*>(&h);
}
__device__ __forceinline__ float2 h2f2(uint32_t u) {
    __half2 h = *reinterpret_cast<__half2*>(&u);
    return __half22float2(h);
}

__global__ __launch_bounds__(256)
void repack_kernel(const float2* __restrict__ src)
{
    int g = blockIdx.x * blockDim.x + threadIdx.x;
    if (g >= TOTAL_SRC) return;
    // D[g].y = e[g+1]: only read when (g, g+1) form an in-level pair, so the
    // global clamp at the array end is the only bound needed (a level's last
    // entry is never a fused-low; cross-level hi halves are never read).
    float2 a = __ldg(&src[g]);
    float2 b = __ldg(&src[min(g + 1, TOTAL_SRC - 1)]);
    g_emb[g] = make_uint2(f22h2(a), f22h2(b));
}

// Load corner pair (i0, i1). If |i0-i1|==1, one 8B load of D[min]; else two
// 4B lo-half loads. (Two-arm divergent structure = measured best; dense lanes
// always take the fused arm.)
__device__ __forceinline__ void pair_load(const uint2* __restrict__ tab,
                                          uint32_t i0, uint32_t i1,
                                          float2& v0, float2& v1)
{
    uint32_t d = i0 - i1;
    if (d == 1u || d == 0xFFFFFFFFu) {
        uint32_t lo = (d == 1u) ? i1 : i0;
        uint2 q = __ldg(&tab[lo]);
        float2 A = h2f2(q.x);   // e[lo]
        float2 B = h2f2(q.y);   // e[lo+1]
        bool sw = (d == 1u);    // i0 is the high index
        v0 = sw ? B : A;
        v1 = sw ? A : B;
    } else {
        const uint32_t* t32 = reinterpret_cast<const uint32_t*>(tab);
        v0 = h2f2(__ldg(&t32[2u * i0]));
        v1 = h2f2(__ldg(&t32[2u * i1]));
    }
}

__global__ __launch_bounds__(256)
void hash_encode_kernel(const float* __restrict__ in,
                        float2* __restrict__ out)
{
    int tid = blockIdx.x * blockDim.x + threadIdx.x;
    if (tid >= NPAIRS) return;

    int b = tid >> 4;
    int l = tid & 15;

    // map [-1,1) -> [0,1)
    float x = (__ldg(&in[b * 3 + 0]) + 1.0f) * 0.5f;
    float y = (__ldg(&in[b * 3 + 1]) + 1.0f) * 0.5f;
    float z = (__ldg(&in[b * 3 + 2]) + 1.0f) * 0.5f;

    uint32_t res = 16u << l;
    float fres = (float)res;

    float px = x * fres, py = y * fres, pz = z * fres;
    float gx = floorf(px), gy = floorf(py), gz = floorf(pz);
    float fx = px - gx,   fy = py - gy,   fz = pz - gz;
    uint32_t ux = (uint32_t)gx, uy = (uint32_t)gy, uz = (uint32_t)gz;

    // hashed-form partials: idx = (ux*1 ^ uy*P1 ^ uz*P2) & (2^19 - 1)
    const uint32_t P1 = 2654435761u;
    const uint32_t P2 = 805459861u;
    uint32_t hx0 = ux;        uint32_t hx1 = ux + 1u;
    uint32_t hy0 = uy * P1;   uint32_t hy1 = hy0 + P1;
    uint32_t hz0 = uz * P2;   uint32_t hz1 = hz0 + P2;

    // dense-form partials: idx = ux + uy*(res+1) + uz*(res+1)^2 (in range,
    // x < 1 strictly). Garbage for hashed lanes; selected away below.
    uint32_t r1 = res + 1u;
    uint32_t r2 = r1 * r1;
    uint32_t sy0 = uy * r1;  uint32_t sy1 = sy0 + r1;
    uint32_t sz0 = uz * r2;  uint32_t sz1 = sz0 + r2;

    bool hashed = (l >= 3);
    const uint2* __restrict__ tab = g_emb + c_off[l];

    // corner c = xbit | (ybit<<1) | (zbit<<2); pair p = ybit | (zbit<<1)
    float2 v[8];
#pragma unroll
    for (int p = 0; p < 4; p++) {
        uint32_t hyz = ((p & 1) ? hy1 : hy0) ^ ((p & 2) ? hz1 : hz0);
        uint32_t ih0 = (hx0 ^ hyz) & 0x7FFFFu;
        uint32_t ih1 = (hx1 ^ hyz) & 0x7FFFFu;
        uint32_t s   = ((p & 1) ? sy1 : sy0) + ((p & 2) ? sz1 : sz0) + ux;
        uint32_t i0 = hashed ? ih0 : s;
        uint32_t i1 = hashed ? ih1 : (s + 1u);
        pair_load(tab, i0, i1, v[2 * p], v[2 * p + 1]);
    }

    // trilinear weights
    float wx[2] = {1.0f - fx, fx};
    float wy[2] = {1.0f - fy, fy};
    float wz[2] = {1.0f - fz, fz};

    float ax = 0.0f, ay = 0.0f;
#pragma unroll
    for (int c = 0; c < 8; c++) {
        float w = wx[c & 1] * wy[(c >> 1) & 1] * wz[c >> 2];
        ax = fmaf(w, v[c].x, ax);
        ay = fmaf(w, v[c].y, ay);
    }

    // streaming store: output is write-once; evict-first keeps the table
    // resident in L2 instead of churning it with output lines.
    __stcs(&out[tid], make_float2(ax, ay));
}

extern "C" void kernel_launch(void* const* d_in, const int* in_sizes, int n_in,
                              void* d_out, int out_size)
{
    const float*  inputs = (const float*)d_in[0];
    const float2* emb    = (const float2*)d_in[1];
    float2*       out    = (float2*)d_out;

    // 1) build fp16 pair-duplicated table. Idempotent, deterministic,
    //    graph-capturable.
    {
        int nthreads = TOTAL_SRC;
        repack_kernel<<<(nthreads + 255) / 256, 256>>>(emb);
    }

    // 2) gather/interpolate
    hash_encode_kernel<<<(NPAIRS + 255) / 256, 256>>>(inputs, out);
}

// round 16
// speedup vs baseline: 1.1755x; 1.0418x over previous
#include <cuda_runtime.h>
#include <cuda_fp16.h>
#include <stdint.h>

// Instant-NGP hash grid encode — fp16 pair-duplicated table, vectorized repack.
// B=524288 points, D=3, L=16 levels, C=2, H=16, hashed table size 2^19.
//
// Evidence trail:
//  - Gather is AT the L1tex scattered-wavefront floor (~187 wf/warp model
//    reproduces 171us exactly). Table entry D[g] = (fp16x2(e[g]),
//    fp16x2(e[g+1])): 8B/entry keeps original 57MB footprint; dense pairs
//    always fuse into one 8B load, hashed pairs fuse with prob 1/2.
//    rel_err 2.98e-4 (fp16 quantization), 3.4x under the 1e-3 gate.
//  - R14's scalar repack cost ~19us vs ~9us for the fp32 rounds (same bytes)
//    — instruction inefficiency. R15: 2 dst entries/thread, float4+float2
//    reads, uint4 store. Tail thread (odd TOTAL_SRC) takes a scalar path to
//    avoid an 8B out-of-bounds float4 read of the input buffer.

#define NPOINTS  524288
#define NLEVELS  16
#define NPAIRS   (NPOINTS * NLEVELS)
#define TOTAL_SRC 7131219

// D[g] = (h2(e[g]), h2(e[g+1])), 8B each, original (unpadded) level offsets.
__device__ __align__(16) uint2 g_emb[TOTAL_SRC];

__constant__ int c_off[16] = {
    0, 4913, 40850, 315475,
    839763, 1364051, 1888339, 2412627,
    2936915, 3461203, 3985491, 4509779,
    5034067, 5558355, 6082643, 6606931
};

__device__ __forceinline__ uint32_t f22h2(float x, float y) {
    __half2 h = __floats2half2_rn(x, y);
    return *reinterpret_cast<uint32_t*>(&h);
}
__device__ __forceinline__ float2 h2f2(uint32_t u) {
    __half2 h = *reinterpret_cast<__half2*>(&u);
    return __half22float2(h);
}

// 2 dst entries per thread: D[2t] = (h(e0), h(e1)); D[2t+1] = (h(e1), h(e2)).
// Hi halves are only consumed for in-level consecutive pairs; level-local
// last indices are odd (never a fused-low), so clamped/garbage hi halves at
// array boundaries are never read.
__global__ __launch_bounds__(256)
void repack_kernel(const float4* __restrict__ src4,
                   const float2* __restrict__ src2)
{
    int t = blockIdx.x * blockDim.x + threadIdx.x;
    int g = t * 2;
    if (g >= TOTAL_SRC) return;

    if (g + 1 < TOTAL_SRC) {
        float4 ab = __ldg(&src4[t]);                   // e[g], e[g+1]
        int gn = g + 2; if (gn > TOTAL_SRC - 1) gn = TOTAL_SRC - 1;
        float2 cc = __ldg(&src2[gn]);                  // e[g+2] (clamped)
        uint32_t h0 = f22h2(ab.x, ab.y);
        uint32_t h1 = f22h2(ab.z, ab.w);
        uint32_t h2v = f22h2(cc.x, cc.y);
        *reinterpret_cast<uint4*>(&g_emb[g]) = make_uint4(h0, h1, h1, h2v);
    } else {
        // tail (TOTAL_SRC odd): scalar read only — no OOB float4
        float2 a = __ldg(&src2[g]);                    // e[g] = last entry
        uint32_t h0 = f22h2(a.x, a.y);
        g_emb[g] = make_uint2(h0, h0);                 // hi half never read
    }
}

// Load corner pair (i0, i1). If |i0-i1|==1, one 8B load of D[min]; else two
// 4B lo-half loads. (Two-arm divergent structure = measured best; dense lanes
// always take the fused arm.)
__device__ __forceinline__ void pair_load(const uint2* __restrict__ tab,
                                          uint32_t i0, uint32_t i1,
                                          float2& v0, float2& v1)
{
    uint32_t d = i0 - i1;
    if (d == 1u || d == 0xFFFFFFFFu) {
        uint32_t lo = (d == 1u) ? i1 : i0;
        uint2 q = __ldg(&tab[lo]);
        float2 A = h2f2(q.x);   // e[lo]
        float2 B = h2f2(q.y);   // e[lo+1]
        bool sw = (d == 1u);    // i0 is the high index
        v0 = sw ? B : A;
        v1 = sw ? A : B;
    } else {
        const uint32_t* t32 = reinterpret_cast<const uint32_t*>(tab);
        v0 = h2f2(__ldg(&t32[2u * i0]));
        v1 = h2f2(__ldg(&t32[2u * i1]));
    }
}

__global__ __launch_bounds__(256)
void hash_encode_kernel(const float* __restrict__ in,
                        float2* __restrict__ out)
{
    int tid = blockIdx.x * blockDim.x + threadIdx.x;
    if (tid >= NPAIRS) return;

    int b = tid >> 4;
    int l = tid & 15;

    // map [-1,1) -> [0,1)
    float x = (__ldg(&in[b * 3 + 0]) + 1.0f) * 0.5f;
    float y = (__ldg(&in[b * 3 + 1]) + 1.0f) * 0.5f;
    float z = (__ldg(&in[b * 3 + 2]) + 1.0f) * 0.5f;

    uint32_t res = 16u << l;
    float fres = (float)res;

    float px = x * fres, py = y * fres, pz = z * fres;
    float gx = floorf(px), gy = floorf(py), gz = floorf(pz);
    float fx = px - gx,   fy = py - gy,   fz = pz - gz;
    uint32_t ux = (uint32_t)gx, uy = (uint32_t)gy, uz = (uint32_t)gz;

    // hashed-form partials: idx = (ux*1 ^ uy*P1 ^ uz*P2) & (2^19 - 1)
    const uint32_t P1 = 2654435761u;
    const uint32_t P2 = 805459861u;
    uint32_t hx0 = ux;        uint32_t hx1 = ux + 1u;
    uint32_t hy0 = uy * P1;   uint32_t hy1 = hy0 + P1;
    uint32_t hz0 = uz * P2;   uint32_t hz1 = hz0 + P2;

    // dense-form partials: idx = ux + uy*(res+1) + uz*(res+1)^2 (in range,
    // x < 1 strictly). Garbage for hashed lanes; selected away below.
    uint32_t r1 = res + 1u;
    uint32_t r2 = r1 * r1;
    uint32_t sy0 = uy * r1;  uint32_t sy1 = sy0 + r1;
    uint32_t sz0 = uz * r2;  uint32_t sz1 = sz0 + r2;

    bool hashed = (l >= 3);
    const uint2* __restrict__ tab = g_emb + c_off[l];

    // corner c = xbit | (ybit<<1) | (zbit<<2); pair p = ybit | (zbit<<1)
    float2 v[8];
#pragma unroll
    for (int p = 0; p < 4; p++) {
        uint32_t hyz = ((p & 1) ? hy1 : hy0) ^ ((p & 2) ? hz1 : hz0);
        uint32_t ih0 = (hx0 ^ hyz) & 0x7FFFFu;
        uint32_t ih1 = (hx1 ^ hyz) & 0x7FFFFu;
        uint32_t s   = ((p & 1) ? sy1 : sy0) + ((p & 2) ? sz1 : sz0) + ux;
        uint32_t i0 = hashed ? ih0 : s;
        uint32_t i1 = hashed ? ih1 : (s + 1u);
        pair_load(tab, i0, i1, v[2 * p], v[2 * p + 1]);
    }

    // trilinear weights
    float wx[2] = {1.0f - fx, fx};
    float wy[2] = {1.0f - fy, fy};
    float wz[2] = {1.0f - fz, fz};

    float ax = 0.0f, ay = 0.0f;
#pragma unroll
    for (int c = 0; c < 8; c++) {
        float w = wx[c & 1] * wy[(c >> 1) & 1] * wz[c >> 2];
        ax = fmaf(w, v[c].x, ax);
        ay = fmaf(w, v[c].y, ay);
    }

    // streaming store: output is write-once; evict-first keeps the table
    // resident in L2 instead of churning it with output lines.
    __stcs(&out[tid], make_float2(ax, ay));
}

extern "C" void kernel_launch(void* const* d_in, const int* in_sizes, int n_in,
                              void* d_out, int out_size)
{
    const float*  inputs = (const float*)d_in[0];
    const float2* emb    = (const float2*)d_in[1];
    float2*       out    = (float2*)d_out;

    // 1) build fp16 pair-duplicated table (vectorized: 2 entries/thread).
    //    Idempotent, deterministic, graph-capturable.
    {
        int nthreads = (TOTAL_SRC + 1) / 2;
        repack_kernel<<<(nthreads + 255) / 256, 256>>>(
            (const float4*)emb, emb);
    }

    // 2) gather/interpolate
    hash_encode_kernel<<<(NPAIRS + 255) / 256, 256>>>(inputs, out);
}